// round 2
// baseline (speedup 1.0000x reference)
#include <cuda_runtime.h>

// Problem constants (fixed by the reference: T=512 steps, B=64, E=512)
#define T_STEPS 512
#define B_SZ    64
#define E_SZ    512
#define MAXW    64     // max slots overlapping a width-1 read window (d~U(0,1): >62 consecutive near-zero d's is impossible)
#define TB_T    4      // t-tiles per block in the read kernel

// Scratch (static __device__ -- no allocations)
__device__ int   g_lo [B_SZ][T_STEPS];
__device__ int   g_cnt[B_SZ][T_STEPS];
__device__ float g_c  [B_SZ][T_STEPS][MAXW];

// ---------------------------------------------------------------------------
// Kernel 1: per-batch queue recurrence via tape model.
//   A_i   = inclusive cumsum of d          (tape position of slot i's end)
//   SU_t  = inclusive cumsum of u
//   pop_t = SU_t + min_{j<=t}(A_{j-1} - SU_j)   (linearized pop recurrence)
//   c_i^t = max(0, min(A_i, pop_t+1) - max(A_{i-1}, pop_t)), nonzero on a
//           narrow slot window found by binary search.
// All in fp64 to avoid cancellation (A ~ 256, c ~ O(1)).
// ---------------------------------------------------------------------------
__global__ void __launch_bounds__(T_STEPS) queue_coeffs(const float* __restrict__ U,
                                                        const float* __restrict__ D)
{
    const int b    = blockIdx.x;
    const int t    = threadIdx.x;
    const int lane = t & 31;
    const int wid  = t >> 5;            // 16 warps

    __shared__ double sA[T_STEPS];
    __shared__ double sw0[16];
    __shared__ double sw1[16];
    __shared__ double sw2[16];

    const double dval = (double)D[t * B_SZ + b];
    const double uval = (double)U[t * B_SZ + b];

    // ---- inclusive warp scans of d and u ----
    double x  = dval;
    double su = uval;
    #pragma unroll
    for (int o = 1; o < 32; o <<= 1) {
        double y0 = __shfl_up_sync(0xffffffffu, x,  o);
        double y1 = __shfl_up_sync(0xffffffffu, su, o);
        if (lane >= o) { x += y0; su += y1; }
    }
    if (lane == 31) { sw0[wid] = x; sw1[wid] = su; }
    __syncthreads();
    if (t < 16) {
        double y0 = sw0[t], y1 = sw1[t];
        #pragma unroll
        for (int o = 1; o < 16; o <<= 1) {
            double z0 = __shfl_up_sync(0x0000ffffu, y0, o);
            double z1 = __shfl_up_sync(0x0000ffffu, y1, o);
            if (lane >= o) { y0 += z0; y1 += z1; }
        }
        sw0[t] = y0; sw1[t] = y1;
    }
    __syncthreads();
    const double A  = x  + (wid ? sw0[wid - 1] : 0.0);   // inclusive cumsum D
    const double SU = su + (wid ? sw1[wid - 1] : 0.0);   // inclusive cumsum U
    sA[t] = A;
    __syncthreads();

    // ---- prefix-min of g_t = A_{t-1} - SU_t  ->  pop_t ----
    double m = (t ? sA[t - 1] : 0.0) - SU;
    #pragma unroll
    for (int o = 1; o < 32; o <<= 1) {
        double y = __shfl_up_sync(0xffffffffu, m, o);
        if (lane >= o) m = fmin(m, y);
    }
    if (lane == 31) sw2[wid] = m;
    __syncthreads();
    if (t < 16) {
        double y = sw2[t];
        #pragma unroll
        for (int o = 1; o < 16; o <<= 1) {
            double z = __shfl_up_sync(0x0000ffffu, y, o);
            if (lane >= o) y = fmin(y, z);
        }
        sw2[t] = y;
    }
    __syncthreads();
    if (wid) m = fmin(m, sw2[wid - 1]);
    const double pop = SU + m;

    // ---- window extraction: first slot i in [0, t] with A_i > pop ----
    int loI = 0, hiI = t + 1;
    while (loI < hiI) {
        int mid = (loI + hiI) >> 1;
        if (sA[mid] > pop) hiI = mid; else loI = mid + 1;
    }
    int cnt = 0;
    const double lim = pop + 1.0;
    double prev = (loI > 0) ? sA[loI - 1] : 0.0;
    int i = loI;
    while (i <= t && prev < lim && cnt < MAXW) {
        double Ai = sA[i];
        double c  = fmin(Ai, lim) - fmax(prev, pop);
        g_c[b][t][cnt] = (float)fmax(c, 0.0);
        cnt++;
        prev = Ai;
        i++;
    }
    g_lo [b][t] = loI;
    g_cnt[b][t] = cnt;
}

// ---------------------------------------------------------------------------
// Kernel 2: r_t[b,:] = sum_{i in window} c_i * V[i,b,:]
// One block per (b, 4 consecutive t). 128 threads x float4 covers E=512.
// ---------------------------------------------------------------------------
__global__ void __launch_bounds__(128) queue_read(const float* __restrict__ V,
                                                  float* __restrict__ out)
{
    const int b    = blockIdx.x;
    const int t0   = blockIdx.y * TB_T;
    const int tid  = threadIdx.x;
    const int w    = tid >> 5;          // warp 0..3 stages t0+w's coeffs
    const int lane = tid & 31;

    __shared__ float sc [TB_T][MAXW];
    __shared__ int   slo[TB_T], scnt[TB_T];

    {
        const int tt  = t0 + w;
        const int lo  = g_lo [b][tt];
        const int cnt = g_cnt[b][tt];
        if (lane == 0) { slo[w] = lo; scnt[w] = cnt; }
        for (int j = lane; j < cnt; j += 32) sc[w][j] = g_c[b][tt][j];
    }
    __syncthreads();

    int rlo[TB_T], rcnt[TB_T];
    int lomin = 0x7fffffff, himax = 0;
    #pragma unroll
    for (int k = 0; k < TB_T; k++) {
        rlo[k]  = slo[k];
        rcnt[k] = scnt[k];
        if (rcnt[k] > 0) {
            lomin = min(lomin, rlo[k]);
            himax = max(himax, rlo[k] + rcnt[k]);
        }
    }

    float4 acc[TB_T];
    #pragma unroll
    for (int k = 0; k < TB_T; k++) acc[k] = make_float4(0.f, 0.f, 0.f, 0.f);

    const float4* __restrict__ V4 = (const float4*)V;
    for (int s = lomin; s < himax; s++) {
        float4 v = V4[(s * B_SZ + b) * (E_SZ / 4) + tid];
        #pragma unroll
        for (int k = 0; k < TB_T; k++) {
            int rel = s - rlo[k];
            if (rel >= 0 && rel < rcnt[k]) {
                float c = sc[k][rel];
                acc[k].x += c * v.x;
                acc[k].y += c * v.y;
                acc[k].z += c * v.z;
                acc[k].w += c * v.w;
            }
        }
    }

    float4* O4 = (float4*)out;
    #pragma unroll
    for (int k = 0; k < TB_T; k++)
        O4[((t0 + k) * B_SZ + b) * (E_SZ / 4) + tid] = acc[k];
}

// ---------------------------------------------------------------------------
extern "C" void kernel_launch(void* const* d_in, const int* in_sizes, int n_in,
                              void* d_out, int out_size)
{
    const float* V = (const float*)d_in[0];   // [T, B, E]
    const float* U = (const float*)d_in[1];   // [T, B]
    const float* D = (const float*)d_in[2];   // [T, B]
    float* out = (float*)d_out;               // [T, B, E]

    queue_coeffs<<<B_SZ, T_STEPS>>>(U, D);

    dim3 grid(B_SZ, T_STEPS / TB_T);
    queue_read<<<grid, 128>>>(V, out);
}